// round 11
// baseline (speedup 1.0000x reference)
#include <cuda_runtime.h>

#define B 4
#define L 2048
#define H 8
#define D 64
#define S 40
#define NTOP 40
#define BH (B*H)

#define KS 8            // k-splits (256 keys each)
#define NU 8            // u-chunks
#define UPC 5           // u rows per chunk (NU*UPC == NTOP)

#define CCH 64          // cumsum chunks
#define CLEN (L/CCH)    // 32 rows per chunk
#define RPT 4           // cumsum rows per thread
#define SUBG (CLEN/RPT) // 8 subgroups

#define FULLMASK 0xffffffffu

// Scratch (no allocations allowed)
__device__ float g_M[BH * L];
__device__ int   g_top[BH * NTOP];
__device__ float g_cs[BH * CCH * D];
__device__ float g_pl[BH * NTOP * KS];
__device__ float g_pacc[BH * NTOP * KS * D];

__device__ __forceinline__ float4 f4add(float4 a, float4 b) {
    return make_float4(a.x + b.x, a.y + b.y, a.z + b.z, a.w + b.w);
}

// ---------------------------------------------------------------------------
// Kernel 1: M[bh,l] = max_s(Q[l]·K[idx[l,s]]) - (sum_s Q[l]·K[idx[l,s]]) / L
// One warp per (bh,l). Coalesced group-gather: 8 lanes per sample, 4 samples
// per step (nL=4 wavefronts per LDG.128). index_sample is int32 on the wire.
// ---------------------------------------------------------------------------
__global__ void __launch_bounds__(256)
mscore_kernel(const float* __restrict__ Q,
              const float* __restrict__ K,
              const int* __restrict__ idx) {
    int warp = blockIdx.x * 8 + (threadIdx.x >> 5);
    int lane = threadIdx.x & 31;
    int g = lane >> 3, j = lane & 7;
    int l  = warp & (L - 1);
    int bh = warp >> 11;
    int b = bh >> 3, h = bh & 7;

    const float4* q4 = (const float4*)(Q + ((size_t)(b * L + l) * H + h) * D);
    float4 qa = q4[j], qb = q4[8 + j];

    const int* srow = idx + (size_t)l * S;
    int s_lo = srow[lane];
    int s_hi = (lane < 8) ? srow[lane + 32] : 0;

    const float* Kb = K + ((size_t)b * L * H + h) * D;
    float mx = -1e30f, sm = 0.f;

    #pragma unroll
    for (int bt = 0; bt < 10; bt++) {
        int s = bt * 4 + g;
        int ki = (bt < 8) ? __shfl_sync(FULLMASK, s_lo, s)
                          : __shfl_sync(FULLMASK, s_hi, s - 32);
        const float4* k4 = (const float4*)(Kb + (size_t)ki * H * D);
        float4 ka = k4[j], kb = k4[8 + j];
        float d = qa.x*ka.x + qa.y*ka.y + qa.z*ka.z + qa.w*ka.w
                + qb.x*kb.x + qb.y*kb.y + qb.z*kb.z + qb.w*kb.w;
        d += __shfl_down_sync(FULLMASK, d, 4);
        d += __shfl_down_sync(FULLMASK, d, 2);
        d += __shfl_down_sync(FULLMASK, d, 1);
        if (j == 0) { mx = fmaxf(mx, d); sm += d; }
    }

    if (j != 0) { mx = -1e30f; sm = 0.f; }
    mx = fmaxf(mx, __shfl_xor_sync(FULLMASK, mx, 8));
    sm +=          __shfl_xor_sync(FULLMASK, sm, 8);
    mx = fmaxf(mx, __shfl_xor_sync(FULLMASK, mx, 16));
    sm +=          __shfl_xor_sync(FULLMASK, sm, 16);

    if (lane == 0) g_M[bh * L + l] = mx - sm * (1.0f / (float)L);
}

// ---------------------------------------------------------------------------
// Kernel 2: top-40 of M per (bh). 40 block-argmax passes; emits the selected
// index SET sorted ASCENDING (output order-invariant; enables causal chunking).
// ---------------------------------------------------------------------------
__global__ void topk_kernel() {
    int bh = blockIdx.x;
    __shared__ float vals[L];
    __shared__ float wv[8];
    __shared__ int   wi[8];
    __shared__ int   sel[NTOP];
    int tid = threadIdx.x;  // 256

    for (int i = tid; i < L; i += 256) vals[i] = g_M[bh * L + i];
    __syncthreads();

    for (int t = 0; t < NTOP; t++) {
        float bv = -1e38f; int bi = 0;
        for (int i = tid; i < L; i += 256) {
            float v = vals[i];
            if (v > bv) { bv = v; bi = i; }
        }
        #pragma unroll
        for (int off = 16; off; off >>= 1) {
            float ov = __shfl_down_sync(FULLMASK, bv, off);
            int   oi = __shfl_down_sync(FULLMASK, bi, off);
            if (ov > bv || (ov == bv && oi < bi)) { bv = ov; bi = oi; }
        }
        if ((tid & 31) == 0) { wv[tid >> 5] = bv; wi[tid >> 5] = bi; }
        __syncthreads();
        if (tid == 0) {
            float fv = wv[0]; int fi = wi[0];
            #pragma unroll
            for (int w = 1; w < 8; w++)
                if (wv[w] > fv || (wv[w] == fv && wi[w] < fi)) { fv = wv[w]; fi = wi[w]; }
            sel[t] = fi;
            vals[fi] = -1e38f;
        }
        __syncthreads();
    }

    if (tid < NTOP) {
        int mine = sel[tid], r = 0;
        #pragma unroll
        for (int i = 0; i < NTOP; i++) r += (sel[i] < mine);
        g_top[bh * NTOP + r] = mine;
    }
}

// ---------------------------------------------------------------------------
// Kernel 3a: per-chunk sums of V. grid (CCH, BH), block 128.
// ---------------------------------------------------------------------------
__global__ void cumsumA_kernel(const float* __restrict__ V) {
    int c = blockIdx.x, bh = blockIdx.y;
    int b = bh >> 3, h = bh & 7;
    int tid = threadIdx.x, rg = tid >> 4, f4 = tid & 15;
    const int RS = H * D / 4;

    const float4* vb = (const float4*)(V + ((size_t)(b * L + c * CLEN + rg * RPT) * H + h) * D) + f4;
    float4 s = vb[0];
    #pragma unroll
    for (int i = 1; i < RPT; i++) s = f4add(s, vb[(size_t)i * RS]);

    __shared__ float4 sm[SUBG][16];
    sm[rg][f4] = s;
    __syncthreads();
    if (rg == 0) {
        float4 t = sm[0][f4];
        #pragma unroll
        for (int i = 1; i < SUBG; i++) t = f4add(t, sm[i][f4]);
        ((float4*)g_cs)[(bh * CCH + c) * 16 + f4] = t;
    }
}

// ---------------------------------------------------------------------------
// Kernel 3b: scan. grid (CCH, BH), block 128.
// ---------------------------------------------------------------------------
__global__ void cumsumC_kernel(const float* __restrict__ V, float* __restrict__ out) {
    int c = blockIdx.x, bh = blockIdx.y;
    int b = bh >> 3, h = bh & 7;
    int tid = threadIdx.x, rg = tid >> 4, f4 = tid & 15;
    const int RS = H * D / 4;

    const float4* vb = (const float4*)(V + ((size_t)(b * L + c * CLEN + rg * RPT) * H + h) * D) + f4;
    float4 v0 = vb[0], v1 = vb[RS], v2 = vb[2 * RS], v3 = vb[3 * RS];
    float4 p = f4add(f4add(v0, v1), f4add(v2, v3));

    __shared__ float4 sp[SUBG][16];
    __shared__ float4 sg[SUBG][16];
    sp[rg][f4] = p;

    float4 gacc = make_float4(0.f, 0.f, 0.f, 0.f);
    const float4* cs4 = (const float4*)g_cs + (size_t)bh * CCH * 16 + f4;
    for (int cc = rg; cc < c; cc += SUBG) gacc = f4add(gacc, cs4[cc * 16]);
    sg[rg][f4] = gacc;
    __syncthreads();

    float4 run = make_float4(0.f, 0.f, 0.f, 0.f);
    #pragma unroll
    for (int i = 0; i < SUBG; i++) {
        run = f4add(run, sg[i][f4]);
        if (i < rg) run = f4add(run, sp[i][f4]);
    }

    float4 o0 = f4add(run, v0);
    float4 o1 = f4add(o0, v1);
    float4 o2 = f4add(o1, v2);
    float4 o3 = f4add(o2, v3);

    float4* ob = (float4*)(out + ((size_t)bh * L + c * CLEN + rg * RPT) * D) + f4;
    ob[0] = o0; ob[16] = o1; ob[32] = o2; ob[48] = o3;
}

// ---------------------------------------------------------------------------
// Kernel 4: attention partials, UNNORMALIZED exp (no online max: |s|<~6, so
// exp can't overflow fp32; result Σp·v/Σp is mathematically identical).
// grid (KS, NU, BH), block 256. Block = 5 consecutive (ascending) u's ×
// 256 keys. Early exit when ks*256 > lu_hi (real causal saving, ~44% of
// blocks). Warp w owns keys [ks*256+32w, +32); group of 8 lanes per key.
// Block merges its 32 group partials in smem, writes one partial per (u,ks).
// ---------------------------------------------------------------------------
__global__ void __launch_bounds__(256)
attn_part_kernel(const float* __restrict__ Q,
                 const float* __restrict__ K,
                 const float* __restrict__ V) {
    int ks = blockIdx.x, uc = blockIdx.y, bh = blockIdx.z;
    int b = bh >> 3, h = bh & 7;
    int u0 = uc * UPC;

    int lu[UPC];
    #pragma unroll
    for (int iu = 0; iu < UPC; iu++) lu[iu] = g_top[bh * NTOP + u0 + iu];
    int lu_hi = lu[UPC - 1];
    if (ks * 256 > lu_hi) return;          // causal early exit

    int tid = threadIdx.x, w = tid >> 5, lane = tid & 31;
    int g = lane >> 3, j = lane & 7;

    // Q slices: lane j holds floats [4j..4j+4) and [32+4j..32+4j+4) per u
    float4 qa[UPC], qb[UPC];
    #pragma unroll
    for (int iu = 0; iu < UPC; iu++) {
        const float4* q4 = (const float4*)(Q + ((size_t)(b * L + lu[iu]) * H + h) * D);
        qa[iu] = q4[j]; qb[iu] = q4[8 + j];
    }

    float lsum[UPC];
    float4 aa[UPC], ab[UPC];
    #pragma unroll
    for (int iu = 0; iu < UPC; iu++) {
        lsum[iu] = 0.f;
        aa[iu] = make_float4(0.f, 0.f, 0.f, 0.f);
        ab[iu] = make_float4(0.f, 0.f, 0.f, 0.f);
    }

    int base = ks * 256 + w * 32;
    int nst = 0;
    if (base <= lu_hi) {
        int span = lu_hi + 1 - base;
        if (span > 32) span = 32;
        nst = (span + 3) >> 2;
    }

    const float* Kb = K + ((size_t)b * L * H + h) * D;
    const float* Vb = V + ((size_t)b * L * H + h) * D;

    for (int st = 0; st < nst; st++) {
        int t = base + st * 4 + g;
        const float4* k4 = (const float4*)(Kb + (size_t)t * H * D);
        const float4* v4 = (const float4*)(Vb + (size_t)t * H * D);
        float4 ka = k4[j], kb = k4[8 + j];
        float4 va = v4[j], vb = v4[8 + j];

        #pragma unroll
        for (int iu = 0; iu < UPC; iu++) {
            float d = qa[iu].x*ka.x + qa[iu].y*ka.y + qa[iu].z*ka.z + qa[iu].w*ka.w
                    + qb[iu].x*kb.x + qb[iu].y*kb.y + qb[iu].z*kb.z + qb[iu].w*kb.w;
            d += __shfl_xor_sync(FULLMASK, d, 4);
            d += __shfl_xor_sync(FULLMASK, d, 2);
            d += __shfl_xor_sync(FULLMASK, d, 1);   // all 8 lanes hold the dot
            float s = (t <= lu[iu]) ? d * 0.125f : -3e38f;
            float p = __expf(s);                    // masked -> 0
            lsum[iu] += p;
            aa[iu].x += p * va.x; aa[iu].y += p * va.y;
            aa[iu].z += p * va.z; aa[iu].w += p * va.w;
            ab[iu].x += p * vb.x; ab[iu].y += p * vb.y;
            ab[iu].z += p * vb.z; ab[iu].w += p * vb.w;
        }
    }

    // merge 32 group partials (slot = w*4+g) in smem
    __shared__ float s_l[UPC][32];
    __shared__ float s_acc[UPC][32][64];
    int gs = w * 4 + g;
    #pragma unroll
    for (int iu = 0; iu < UPC; iu++) {
        if (j == 0) s_l[iu][gs] = lsum[iu];
        *(float4*)&s_acc[iu][gs][4 * j]      = aa[iu];
        *(float4*)&s_acc[iu][gs][32 + 4 * j] = ab[iu];
    }
    __syncthreads();

    for (int i = tid; i < UPC * 64; i += 256) {
        int iu = i >> 6, d = i & 63;
        float a = 0.f;
        #pragma unroll
        for (int gsi = 0; gsi < 32; gsi++) a += s_acc[iu][gsi][d];
        g_pacc[((size_t)(bh * NTOP + u0 + iu) * KS + ks) * D + d] = a;
    }
    if (tid < UPC) {
        float lt = 0.f;
        #pragma unroll
        for (int gsi = 0; gsi < 32; gsi++) lt += s_l[tid][gsi];
        g_pl[(size_t)(bh * NTOP + u0 + tid) * KS + ks] = lt;
    }
}

// ---------------------------------------------------------------------------
// Kernel 5: combine valid ks partials (plain sums), normalize, scatter.
// Only ks with ks*256 <= lu_hi(uc) were written; sum exactly those.
// ---------------------------------------------------------------------------
__global__ void attn_combine_kernel(float* __restrict__ out) {
    int u = blockIdx.x, bh = blockIdx.y;
    int d = threadIdx.x;   // 64
    int uc = u / UPC;
    int lu_hi = g_top[bh * NTOP + uc * UPC + (UPC - 1)];
    int nks = (lu_hi >> 8) + 1;

    size_t base = (size_t)(bh * NTOP + u) * KS;
    float acc = 0.f, lt = 0.f;
    for (int p = 0; p < nks; p++) {
        acc += g_pacc[(base + p) * D + d];
        lt  += g_pl[base + p];
    }
    int lu = g_top[bh * NTOP + u];
    out[((size_t)bh * L + lu) * D + d] = acc / lt;
}

// ---------------------------------------------------------------------------
extern "C" void kernel_launch(void* const* d_in, const int* in_sizes, int n_in,
                              void* d_out, int out_size) {
    const float* Q   = (const float*)d_in[0];
    const float* K   = (const float*)d_in[1];
    const float* V   = (const float*)d_in[2];
    const int*   idx = (const int*)d_in[3];
    float*       out = (float*)d_out;

    mscore_kernel<<<BH * L / 8, 256>>>(Q, K, idx);
    topk_kernel  <<<BH, 256>>>();
    cumsumA_kernel<<<dim3(CCH, BH), SUBG * 16>>>(V);
    cumsumC_kernel<<<dim3(CCH, BH), SUBG * 16>>>(V, out);
    attn_part_kernel<<<dim3(KS, NU, BH), 256>>>(Q, K, V);
    attn_combine_kernel<<<dim3(NTOP, BH), D>>>(out);
}

// round 12
// speedup vs baseline: 1.0202x; 1.0202x over previous
#include <cuda_runtime.h>

#define B 4
#define L 2048
#define H 8
#define D 64
#define S 40
#define NTOP 40
#define BH (B*H)

#define KS 8            // k-splits (256 keys each)
#define NU 8            // u-chunks
#define UPC 5           // u rows per chunk (NU*UPC == NTOP)

#define CCH 64          // cumsum chunks
#define CLEN (L/CCH)    // 32 rows per chunk

#define MS_BLOCKS (BH*L/8)   // 8192 mscore blocks in K1
#define CA_BLOCKS (CCH*BH/2) // 1024 cumsumA blocks (2 chunks each) in K1

#define FULLMASK 0xffffffffu

// Scratch (no allocations allowed)
__device__ float g_M[BH * L];
__device__ int   g_top[BH * NTOP];
__device__ float g_cs[BH * CCH * D];
__device__ float g_pl[BH * NTOP * KS];
__device__ float g_pacc[BH * NTOP * KS * D];

__device__ __forceinline__ float4 f4add(float4 a, float4 b) {
    return make_float4(a.x + b.x, a.y + b.y, a.z + b.z, a.w + b.w);
}

// ---------------------------------------------------------------------------
// K1: fused mscore ∪ cumsumA. Role by blockIdx.x (block-uniform branch).
//
// mscore role (blocks [0, MS_BLOCKS)): M partial inputs.
//   One warp per (bh,l). Coalesced group-gather: 8 lanes per sample, 4
//   samples per step. index_sample is int32 on the wire (JAX x64 downcast).
// cumsumA role (blocks [MS_BLOCKS, +CA_BLOCKS)): per-chunk sums of V.
//   256 threads = 2 chunks x (8 subgroups x 16 float4-lanes), 4 rows/thread.
// ---------------------------------------------------------------------------
__global__ void __launch_bounds__(256)
k1_mscore_cumsumA(const float* __restrict__ Q,
                  const float* __restrict__ K,
                  const int* __restrict__ idx,
                  const float* __restrict__ V) {
    if (blockIdx.x < MS_BLOCKS) {
        // ------------------- mscore -------------------
        int warp = blockIdx.x * 8 + (threadIdx.x >> 5);
        int lane = threadIdx.x & 31;
        int g = lane >> 3, j = lane & 7;
        int l  = warp & (L - 1);
        int bh = warp >> 11;
        int b = bh >> 3, h = bh & 7;

        const float4* q4 = (const float4*)(Q + ((size_t)(b * L + l) * H + h) * D);
        float4 qa = q4[j], qb = q4[8 + j];

        const int* srow = idx + (size_t)l * S;
        int s_lo = srow[lane];
        int s_hi = (lane < 8) ? srow[lane + 32] : 0;

        const float* Kb = K + ((size_t)b * L * H + h) * D;
        float mx = -1e30f, sm = 0.f;

        #pragma unroll
        for (int bt = 0; bt < 10; bt++) {
            int s = bt * 4 + g;
            int ki = (bt < 8) ? __shfl_sync(FULLMASK, s_lo, s)
                              : __shfl_sync(FULLMASK, s_hi, s - 32);
            const float4* k4 = (const float4*)(Kb + (size_t)ki * H * D);
            float4 ka = k4[j], kb = k4[8 + j];
            float d = qa.x*ka.x + qa.y*ka.y + qa.z*ka.z + qa.w*ka.w
                    + qb.x*kb.x + qb.y*kb.y + qb.z*kb.z + qb.w*kb.w;
            d += __shfl_down_sync(FULLMASK, d, 4);
            d += __shfl_down_sync(FULLMASK, d, 2);
            d += __shfl_down_sync(FULLMASK, d, 1);
            if (j == 0) { mx = fmaxf(mx, d); sm += d; }
        }

        if (j != 0) { mx = -1e30f; sm = 0.f; }
        mx = fmaxf(mx, __shfl_xor_sync(FULLMASK, mx, 8));
        sm +=          __shfl_xor_sync(FULLMASK, sm, 8);
        mx = fmaxf(mx, __shfl_xor_sync(FULLMASK, mx, 16));
        sm +=          __shfl_xor_sync(FULLMASK, sm, 16);

        if (lane == 0) g_M[bh * L + l] = mx - sm * (1.0f / (float)L);
    } else {
        // ------------------- cumsumA -------------------
        __shared__ float4 sa[2][8][16];
        int cb = blockIdx.x - MS_BLOCKS;        // 0..1023
        int tid = threadIdx.x;
        int half = tid >> 7;                    // which of 2 chunks
        int t = tid & 127;
        int cc2 = cb * 2 + half;                // 0..2047
        int c = cc2 & (CCH - 1), bh = cc2 >> 6;
        int b = bh >> 3, h = bh & 7;
        int rg = t >> 4, f4 = t & 15;
        const int RS = H * D / 4;

        const float4* vb = (const float4*)(V + ((size_t)(b * L + c * CLEN + rg * 4) * H + h) * D) + f4;
        float4 s = vb[0];
        #pragma unroll
        for (int i = 1; i < 4; i++) s = f4add(s, vb[(size_t)i * RS]);

        sa[half][rg][f4] = s;
        __syncthreads();
        if (rg == 0) {
            float4 tt = sa[half][0][f4];
            #pragma unroll
            for (int i = 1; i < 8; i++) tt = f4add(tt, sa[half][i][f4]);
            ((float4*)g_cs)[(bh * CCH + c) * 16 + f4] = tt;
        }
    }
}

// ---------------------------------------------------------------------------
// K2: fused topk ∪ cumsumC. Role by blockIdx.x (block-uniform branch).
//
// topk role (blocks [0, BH)): top-40 of M; 40 block-argmax passes; emits
//   the selected set sorted ASCENDING (output order-invariant).
// cumsumC role (blocks [BH, +CCH*BH)): scan. 256 threads = 16 subgroups x
//   16 float4-lanes, 2 rows/thread; distributed sum of preceding chunk-sums.
// ---------------------------------------------------------------------------
__global__ void __launch_bounds__(256)
k2_topk_cumsumC(const float* __restrict__ V, float* __restrict__ out) {
    __shared__ __align__(16) char pool[8448];
    int tid = threadIdx.x;

    if (blockIdx.x < BH) {
        // ------------------- topk -------------------
        float* vals = (float*)pool;             // 2048 floats
        float* wv   = (float*)(pool + 8192);    // 8
        int*   wi   = (int*)(pool + 8224);      // 8
        int*   sel  = (int*)(pool + 8256);      // 40
        int bh = blockIdx.x;

        for (int i = tid; i < L; i += 256) vals[i] = g_M[bh * L + i];
        __syncthreads();

        for (int t = 0; t < NTOP; t++) {
            float bv = -1e38f; int bi = 0;
            for (int i = tid; i < L; i += 256) {
                float v = vals[i];
                if (v > bv) { bv = v; bi = i; }
            }
            #pragma unroll
            for (int off = 16; off; off >>= 1) {
                float ov = __shfl_down_sync(FULLMASK, bv, off);
                int   oi = __shfl_down_sync(FULLMASK, bi, off);
                if (ov > bv || (ov == bv && oi < bi)) { bv = ov; bi = oi; }
            }
            if ((tid & 31) == 0) { wv[tid >> 5] = bv; wi[tid >> 5] = bi; }
            __syncthreads();
            if (tid == 0) {
                float fv = wv[0]; int fi = wi[0];
                #pragma unroll
                for (int w = 1; w < 8; w++)
                    if (wv[w] > fv || (wv[w] == fv && wi[w] < fi)) { fv = wv[w]; fi = wi[w]; }
                sel[t] = fi;
                vals[fi] = -1e38f;
            }
            __syncthreads();
        }

        if (tid < NTOP) {
            int mine = sel[tid], r = 0;
            #pragma unroll
            for (int i = 0; i < NTOP; i++) r += (sel[i] < mine);
            g_top[bh * NTOP + r] = mine;
        }
    } else {
        // ------------------- cumsumC -------------------
        float4 (*sp)[16] = (float4(*)[16])pool;            // [16][16]
        float4 (*sg)[16] = (float4(*)[16])(pool + 4096);   // [16][16]
        int cb = blockIdx.x - BH;               // 0..2047
        int c = cb & (CCH - 1), bh = cb >> 6;
        int b = bh >> 3, h = bh & 7;
        int rg = tid >> 4, f4 = tid & 15;       // 16 subgroups, 2 rows each
        const int RS = H * D / 4;

        const float4* vb = (const float4*)(V + ((size_t)(b * L + c * CLEN + rg * 2) * H + h) * D) + f4;
        float4 v0 = vb[0], v1 = vb[RS];
        sp[rg][f4] = f4add(v0, v1);

        float4 gacc = make_float4(0.f, 0.f, 0.f, 0.f);
        const float4* cs4 = (const float4*)g_cs + (size_t)bh * CCH * 16 + f4;
        for (int cc = rg; cc < c; cc += 16) gacc = f4add(gacc, cs4[cc * 16]);
        sg[rg][f4] = gacc;
        __syncthreads();

        float4 run = make_float4(0.f, 0.f, 0.f, 0.f);
        #pragma unroll
        for (int i = 0; i < 16; i++) {
            run = f4add(run, sg[i][f4]);
            if (i < rg) run = f4add(run, sp[i][f4]);
        }

        float4 o0 = f4add(run, v0);
        float4 o1 = f4add(o0, v1);

        float4* ob = (float4*)(out + ((size_t)bh * L + c * CLEN + rg * 2) * D) + f4;
        ob[0] = o0; ob[16] = o1;
    }
}

// ---------------------------------------------------------------------------
// K3: attention partials, UNNORMALIZED exp (no online max: |s|<~6 so exp
// can't overflow fp32; Σp·v/Σp is mathematically identical to softmax).
// grid (KS, NU, BH), block 256. Causal early exit when ks*256 > lu_hi.
// ---------------------------------------------------------------------------
__global__ void __launch_bounds__(256)
attn_part_kernel(const float* __restrict__ Q,
                 const float* __restrict__ K,
                 const float* __restrict__ V) {
    int ks = blockIdx.x, uc = blockIdx.y, bh = blockIdx.z;
    int b = bh >> 3, h = bh & 7;
    int u0 = uc * UPC;

    int lu[UPC];
    #pragma unroll
    for (int iu = 0; iu < UPC; iu++) lu[iu] = g_top[bh * NTOP + u0 + iu];
    int lu_hi = lu[UPC - 1];
    if (ks * 256 > lu_hi) return;          // causal early exit

    int tid = threadIdx.x, w = tid >> 5, lane = tid & 31;
    int g = lane >> 3, j = lane & 7;

    float4 qa[UPC], qb[UPC];
    #pragma unroll
    for (int iu = 0; iu < UPC; iu++) {
        const float4* q4 = (const float4*)(Q + ((size_t)(b * L + lu[iu]) * H + h) * D);
        qa[iu] = q4[j]; qb[iu] = q4[8 + j];
    }

    float lsum[UPC];
    float4 aa[UPC], ab[UPC];
    #pragma unroll
    for (int iu = 0; iu < UPC; iu++) {
        lsum[iu] = 0.f;
        aa[iu] = make_float4(0.f, 0.f, 0.f, 0.f);
        ab[iu] = make_float4(0.f, 0.f, 0.f, 0.f);
    }

    int base = ks * 256 + w * 32;
    int nst = 0;
    if (base <= lu_hi) {
        int span = lu_hi + 1 - base;
        if (span > 32) span = 32;
        nst = (span + 3) >> 2;
    }

    const float* Kb = K + ((size_t)b * L * H + h) * D;
    const float* Vb = V + ((size_t)b * L * H + h) * D;

    for (int st = 0; st < nst; st++) {
        int t = base + st * 4 + g;
        const float4* k4 = (const float4*)(Kb + (size_t)t * H * D);
        const float4* v4 = (const float4*)(Vb + (size_t)t * H * D);
        float4 ka = k4[j], kb = k4[8 + j];
        float4 va = v4[j], vb = v4[8 + j];

        #pragma unroll
        for (int iu = 0; iu < UPC; iu++) {
            float d = qa[iu].x*ka.x + qa[iu].y*ka.y + qa[iu].z*ka.z + qa[iu].w*ka.w
                    + qb[iu].x*kb.x + qb[iu].y*kb.y + qb[iu].z*kb.z + qb[iu].w*kb.w;
            d += __shfl_xor_sync(FULLMASK, d, 4);
            d += __shfl_xor_sync(FULLMASK, d, 2);
            d += __shfl_xor_sync(FULLMASK, d, 1);
            float s = (t <= lu[iu]) ? d * 0.125f : -3e38f;
            float p = __expf(s);
            lsum[iu] += p;
            aa[iu].x += p * va.x; aa[iu].y += p * va.y;
            aa[iu].z += p * va.z; aa[iu].w += p * va.w;
            ab[iu].x += p * vb.x; ab[iu].y += p * vb.y;
            ab[iu].z += p * vb.z; ab[iu].w += p * vb.w;
        }
    }

    __shared__ float s_l[UPC][32];
    __shared__ float s_acc[UPC][32][64];
    int gs = w * 4 + g;
    #pragma unroll
    for (int iu = 0; iu < UPC; iu++) {
        if (j == 0) s_l[iu][gs] = lsum[iu];
        *(float4*)&s_acc[iu][gs][4 * j]      = aa[iu];
        *(float4*)&s_acc[iu][gs][32 + 4 * j] = ab[iu];
    }
    __syncthreads();

    for (int i = tid; i < UPC * 64; i += 256) {
        int iu = i >> 6, d = i & 63;
        float a = 0.f;
        #pragma unroll
        for (int gsi = 0; gsi < 32; gsi++) a += s_acc[iu][gsi][d];
        g_pacc[((size_t)(bh * NTOP + u0 + iu) * KS + ks) * D + d] = a;
    }
    if (tid < UPC) {
        float lt = 0.f;
        #pragma unroll
        for (int gsi = 0; gsi < 32; gsi++) lt += s_l[tid][gsi];
        g_pl[(size_t)(bh * NTOP + u0 + tid) * KS + ks] = lt;
    }
}

// ---------------------------------------------------------------------------
// K4: combine valid ks partials (plain sums), normalize, scatter.
// ---------------------------------------------------------------------------
__global__ void attn_combine_kernel(float* __restrict__ out) {
    int u = blockIdx.x, bh = blockIdx.y;
    int d = threadIdx.x;   // 64
    int uc = u / UPC;
    int lu_hi = g_top[bh * NTOP + uc * UPC + (UPC - 1)];
    int nks = (lu_hi >> 8) + 1;

    size_t base = (size_t)(bh * NTOP + u) * KS;
    float acc = 0.f, lt = 0.f;
    for (int p = 0; p < nks; p++) {
        acc += g_pacc[(base + p) * D + d];
        lt  += g_pl[base + p];
    }
    int lu = g_top[bh * NTOP + u];
    out[((size_t)bh * L + lu) * D + d] = acc / lt;
}

// ---------------------------------------------------------------------------
extern "C" void kernel_launch(void* const* d_in, const int* in_sizes, int n_in,
                              void* d_out, int out_size) {
    const float* Q   = (const float*)d_in[0];
    const float* K   = (const float*)d_in[1];
    const float* V   = (const float*)d_in[2];
    const int*   idx = (const int*)d_in[3];
    float*       out = (float*)d_out;

    k1_mscore_cumsumA<<<MS_BLOCKS + CA_BLOCKS, 256>>>(Q, K, idx, V);
    k2_topk_cumsumC  <<<BH + CCH * BH, 256>>>(V, out);
    attn_part_kernel <<<dim3(KS, NU, BH), 256>>>(Q, K, V);
    attn_combine_kernel<<<dim3(NTOP, BH), D>>>(out);
}